// round 13
// baseline (speedup 1.0000x reference)
#include <cuda_runtime.h>
#include <cstdint>
#include <cstddef>

#define B_   32
#define T_   14
#define M_   2048
#define QD   768
#define KVD  1024
#define H_   12
#define HD_  64
#define FF_  3072
#define BT   (B_*T_)      // 448
#define TH   (T_*H_)      // 168
#define EPS_ 1e-5f

// ---------------- scratch (device globals; no allocation allowed) ----------------
__device__ float g_Q[BT*QD];
__device__ float g_Qt[(size_t)B_*TH*KVD];       // 22 MB
__device__ float g_c[B_*TH];
__device__ float g_S[(size_t)B_*TH*M_];         // 44 MB
__device__ float g_Ap[(size_t)H_*BT*KVD];       // 22 MB
__device__ float g_attn[BT*QD];
__device__ float g_x1[BT*QD];
__device__ float g_h[BT*FF_];
__device__ float g_ff[BT*QD];
__device__ float g_p1[2*(size_t)BT*FF_];        // FFN1 split-K partials (11 MB)
__device__ float g_p2[2*(size_t)BT*QD];         // FFN2 split-K partials (2.75 MB)

// ---------------- helpers ----------------
__device__ __forceinline__ void mma_tf32(float* c, const uint32_t* a, uint32_t b0, uint32_t b1) {
    asm volatile(
        "mma.sync.aligned.m16n8k8.row.col.f32.tf32.tf32.f32 "
        "{%0,%1,%2,%3}, {%4,%5,%6,%7}, {%8,%9}, {%0,%1,%2,%3};\n"
        : "+f"(c[0]), "+f"(c[1]), "+f"(c[2]), "+f"(c[3])
        : "r"(a[0]), "r"(a[1]), "r"(a[2]), "r"(a[3]), "r"(b0), "r"(b1));
}

__device__ __forceinline__ void cpa16(uint32_t saddr, const void* g, uint32_t sz) {
    asm volatile("cp.async.cg.shared.global [%0], [%1], 16, %2;"
                 :: "r"(saddr), "l"(g), "r"(sz));
}
__device__ __forceinline__ void cpa_commit() { asm volatile("cp.async.commit_group;"); }
__device__ __forceinline__ void cpa_wait2()  { asm volatile("cp.async.wait_group 2;"); }
__device__ __forceinline__ void cpa_wait1()  { asm volatile("cp.async.wait_group 1;"); }
__device__ __forceinline__ void cpa_wait0()  { asm volatile("cp.async.wait_group 0;"); }

// ---- smem layouts (uint32 words) ----
#define SC_A_STRIDE 36
#define SC_B_STRIDE 36
#define SC_A_WORDS  (64*SC_A_STRIDE)
#define SC_B_WORDS  (256*SC_B_STRIDE)
#define SC_SMEM_BYTES ((2*SC_A_WORDS + 2*SC_B_WORDS)*4)    // 92160

#define AP_B_STRIDE 264
#define AP_A_WORDS  (64*SC_A_STRIDE)
#define AP_B_WORDS  (32*AP_B_STRIDE)
#define AP_SMEM_BYTES ((2*AP_A_WORDS + 2*AP_B_WORDS)*4)    // 86016

#define A2_A_WORDS   (96*36)
#define A2_B_WORDS   (32*AP_B_STRIDE)
#define A2_STAGE     (A2_A_WORDS + A2_B_WORDS)
#define A2_SMEM_BYTES (4*A2_STAGE*4)         // 190464

// ---------------- Q projection: one GEMM per expert-token t ----------------
__global__ __launch_bounds__(256) void qproj_kernel(
    const float* __restrict__ X, const float* __restrict__ WQ,
    const float* __restrict__ bQ, float* __restrict__ Q)
{
    int t = blockIdx.x;
    int colBase = blockIdx.y * 128;
    __shared__ float As[32][33];
    __shared__ float Bs[32][132];
    int tid = threadIdx.x;
    int r0 = (tid >> 5) * 4;
    int c0 = (tid & 31) * 4;
    float acc[4][4];
    #pragma unroll
    for (int i = 0; i < 4; i++)
        #pragma unroll
        for (int j = 0; j < 4; j++) acc[i][j] = 0.f;

    const float* Wt = WQ + (size_t)t * QD * QD;
    for (int k0 = 0; k0 < QD; k0 += 32) {
        {
            int r = tid >> 3, c4 = (tid & 7) << 2;
            float4 v = *(const float4*)&X[(size_t)(r*T_ + t)*QD + k0 + c4];
            As[r][c4+0] = v.x; As[r][c4+1] = v.y; As[r][c4+2] = v.z; As[r][c4+3] = v.w;
        }
        #pragma unroll
        for (int i = 0; i < 4; i++) {
            int idx = tid + i * 256;
            int r = idx >> 5, c4 = (idx & 31) << 2;
            float4 v = *(const float4*)&Wt[(size_t)(k0 + r)*QD + colBase + c4];
            Bs[r][c4+0] = v.x; Bs[r][c4+1] = v.y; Bs[r][c4+2] = v.z; Bs[r][c4+3] = v.w;
        }
        __syncthreads();
        #pragma unroll
        for (int kk = 0; kk < 32; kk++) {
            float a[4];
            #pragma unroll
            for (int i = 0; i < 4; i++) a[i] = As[r0+i][kk];
            float4 b4 = *(float4*)&Bs[kk][c0];
            float bb[4] = {b4.x, b4.y, b4.z, b4.w};
            #pragma unroll
            for (int i = 0; i < 4; i++)
                #pragma unroll
                for (int j = 0; j < 4; j++) acc[i][j] += a[i]*bb[j];
        }
        __syncthreads();
    }
    #pragma unroll
    for (int i = 0; i < 4; i++) {
        int bt = (r0 + i)*T_ + t;
        #pragma unroll
        for (int j = 0; j < 4; j++) {
            int c = colBase + c0 + j;
            Q[(size_t)bt*QD + c] = acc[i][j] + bQ[t*QD + c];
        }
    }
}

// ---------------- Qt[b,t,h,e] = sum_d Q[bt, h*64+d] * WK[e, h*64+d] ----------------
__global__ __launch_bounds__(256) void qt_kernel(
    const float* __restrict__ Q, const float* __restrict__ WK,
    float* __restrict__ Qt)
{
    int h  = blockIdx.x;
    int rt = blockIdx.y;
    int et = blockIdx.z;
    __shared__ float Asq[64][65];
    __shared__ float Bsq[64][65];
    int tid = threadIdx.x;
    #pragma unroll
    for (int it = 0; it < 4; it++) {
        int id = tid + it * 256;
        int r = id >> 4, c4 = (id & 15) << 2;
        float4 v = *(const float4*)&Q[(size_t)(rt*64 + r)*QD + h*HD_ + c4];
        Asq[r][c4+0] = v.x; Asq[r][c4+1] = v.y; Asq[r][c4+2] = v.z; Asq[r][c4+3] = v.w;
        float4 w = *(const float4*)&WK[(size_t)(et*64 + r)*QD + h*HD_ + c4];
        Bsq[r][c4+0] = w.x; Bsq[r][c4+1] = w.y; Bsq[r][c4+2] = w.z; Bsq[r][c4+3] = w.w;
    }
    __syncthreads();
    int r0 = (tid >> 4) * 4, e0 = (tid & 15) * 4;
    float acc[4][4];
    #pragma unroll
    for (int i = 0; i < 4; i++)
        #pragma unroll
        for (int j = 0; j < 4; j++) acc[i][j] = 0.f;
    #pragma unroll 8
    for (int d = 0; d < 64; d++) {
        float a[4], b[4];
        #pragma unroll
        for (int i = 0; i < 4; i++) a[i] = Asq[r0+i][d];
        #pragma unroll
        for (int j = 0; j < 4; j++) b[j] = Bsq[e0+j][d];
        #pragma unroll
        for (int i = 0; i < 4; i++)
            #pragma unroll
            for (int j = 0; j < 4; j++) acc[i][j] += a[i]*b[j];
    }
    #pragma unroll
    for (int i = 0; i < 4; i++) {
        int bt = rt*64 + r0 + i;
        int b  = bt / T_, t = bt % T_;
        float* dst = Qt + ((size_t)(b*TH + t*H_ + h))*KVD + et*64 + e0;
        #pragma unroll
        for (int j = 0; j < 4; j++) dst[j] = acc[i][j];
    }
}

// ---------------- c row constant ----------------
__global__ __launch_bounds__(32) void crow_kernel(
    const float* __restrict__ Q, const float* __restrict__ bK, float* __restrict__ c)
{
    int bt = blockIdx.x, h = blockIdx.y;
    int lane = threadIdx.x;
    float s = Q[(size_t)bt*QD + h*HD_ + lane]      * bK[h*HD_ + lane]
            + Q[(size_t)bt*QD + h*HD_ + 32 + lane] * bK[h*HD_ + 32 + lane];
    #pragma unroll
    for (int o = 16; o > 0; o >>= 1) s += __shfl_down_sync(0xffffffffu, s, o);
    if (lane == 0) {
        int b = bt / T_, t = bt % T_;
        c[b*TH + t*H_ + h] = s;
    }
}

// ---------------- scores: S[b] = Qt[b] (168x1024) . X[b]^T -> [168, 2048] ----------------
// block 64x256, warp tile 32x64, 2-stage cp.async, 2 blk/SM. grid (8, 3, B_)
__global__ __launch_bounds__(256, 2) void scores_kernel(
    const float* __restrict__ Qt, const float* __restrict__ X,
    float* __restrict__ S)
{
    extern __shared__ uint32_t sm[];
    uint32_t* As = sm;                       // [2][64][36]
    uint32_t* Bs = sm + 2*SC_A_WORDS;        // [2][256][36]
    uint32_t sA = (uint32_t)__cvta_generic_to_shared(As);
    uint32_t sB = (uint32_t)__cvta_generic_to_shared(Bs);

    int tid = threadIdx.x;
    int lane = tid & 31, w = tid >> 5;
    int warpM = w & 1, warpN = w >> 1;
    int lg = lane >> 2, lt = lane & 3;
    int colBase = blockIdx.x * 256;
    int rowBase = blockIdx.y * 64;
    int b = blockIdx.z;

    const float* Ag = Qt + (size_t)b * TH * KVD;
    const float* Bg = X  + (size_t)b * M_ * KVD;

    float acc[2][8][4];
    #pragma unroll
    for (int mi = 0; mi < 2; mi++)
        #pragma unroll
        for (int ni = 0; ni < 8; ni++)
            #pragma unroll
            for (int q = 0; q < 4; q++) acc[mi][ni][q] = 0.f;

    auto loadA = [&](int kc, int buf) {
        int k0 = kc * 32;
        #pragma unroll
        for (int i = 0; i < 2; i++) {
            int idx = tid + i * 256;
            int r = idx >> 3, c4 = (idx & 7) << 2;
            int gr = rowBase + r;
            int grc = gr < TH ? gr : TH - 1;
            uint32_t sz = gr < TH ? 16u : 0u;
            cpa16(sA + ((buf*SC_A_WORDS + r*SC_A_STRIDE + c4) << 2),
                  Ag + (size_t)grc*KVD + k0 + c4, sz);
        }
    };
    auto loadB = [&](int kc, int buf) {
        int k0 = kc * 32;
        #pragma unroll
        for (int i = 0; i < 8; i++) {
            int idx = tid + i * 256;
            int r = idx >> 3, c4 = (idx & 7) << 2;
            cpa16(sB + ((buf*SC_B_WORDS + r*SC_B_STRIDE + c4) << 2),
                  Bg + (size_t)(colBase + r)*KVD + k0 + c4, 16u);
        }
    };

    const int NC = KVD / 32;
    loadA(0, 0); loadB(0, 0); cpa_commit();
    for (int kc = 0; kc < NC; kc++) {
        int cur = kc & 1;
        if (kc + 1 < NC) {
            loadA(kc+1, cur^1); loadB(kc+1, cur^1); cpa_commit();
            cpa_wait1();
        } else {
            cpa_wait0();
        }
        __syncthreads();
        const uint32_t* Ab = As + cur*SC_A_WORDS;
        const uint32_t* Bb = Bs + cur*SC_B_WORDS;
        #pragma unroll
        for (int ks = 0; ks < 4; ks++) {
            int kb = ks * 8;
            uint32_t a[2][4];
            #pragma unroll
            for (int mi = 0; mi < 2; mi++) {
                int r = warpM*32 + mi*16 + lg;
                a[mi][0] = Ab[r*SC_A_STRIDE + kb + lt];
                a[mi][1] = Ab[(r+8)*SC_A_STRIDE + kb + lt];
                a[mi][2] = Ab[r*SC_A_STRIDE + kb + lt + 4];
                a[mi][3] = Ab[(r+8)*SC_A_STRIDE + kb + lt + 4];
            }
            #pragma unroll
            for (int ni = 0; ni < 8; ni++) {
                int n = warpN*64 + ni*8 + lg;
                uint32_t b0 = Bb[n*SC_B_STRIDE + kb + lt];
                uint32_t b1 = Bb[n*SC_B_STRIDE + kb + lt + 4];
                mma_tf32(acc[0][ni], a[0], b0, b1);
                mma_tf32(acc[1][ni], a[1], b0, b1);
            }
        }
        __syncthreads();
    }

    float* Sg = S + (size_t)b * TH * M_;
    #pragma unroll
    for (int mi = 0; mi < 2; mi++) {
        #pragma unroll
        for (int ni = 0; ni < 8; ni++) {
            int r = rowBase + warpM*32 + mi*16 + lg;
            int cc = colBase + warpN*64 + ni*8 + lt*2;
            if (r < TH) {
                float2 v; v.x = acc[mi][ni][0]; v.y = acc[mi][ni][1];
                *(float2*)&Sg[(size_t)r*M_ + cc] = v;
            }
            if (r + 8 < TH) {
                float2 v; v.x = acc[mi][ni][2]; v.y = acc[mi][ni][3];
                *(float2*)&Sg[(size_t)(r+8)*M_ + cc] = v;
            }
        }
    }
}

// ---------------- softmax (vectorized float4, shuffle reductions) ----------------
__global__ __launch_bounds__(256) void softmax_kernel(
    const float* __restrict__ S, const float* __restrict__ c,
    float* __restrict__ P)
{
    __shared__ float red[8];
    int row = blockIdx.x, tid = threadIdx.x;
    int lane = tid & 31, wid = tid >> 5;
    const float4* s4 = (const float4*)(S + (size_t)row * M_);
    float4*       p4 = (float4*)(P + (size_t)row * M_);
    float cv = c[row];

    float4 v[2];
    float mx = -1e30f;
    #pragma unroll
    for (int i = 0; i < 2; i++) {
        float4 t = s4[tid + i*256];
        t.x = (t.x + cv) * 0.125f; t.y = (t.y + cv) * 0.125f;
        t.z = (t.z + cv) * 0.125f; t.w = (t.w + cv) * 0.125f;
        v[i] = t;
        mx = fmaxf(mx, fmaxf(fmaxf(t.x, t.y), fmaxf(t.z, t.w)));
    }
    #pragma unroll
    for (int o = 16; o > 0; o >>= 1) mx = fmaxf(mx, __shfl_xor_sync(0xffffffffu, mx, o));
    if (lane == 0) red[wid] = mx;
    __syncthreads();
    mx = red[lane & 7];
    #pragma unroll
    for (int o = 4; o > 0; o >>= 1) mx = fmaxf(mx, __shfl_xor_sync(0xffffffffu, mx, o));

    float sum = 0.f;
    #pragma unroll
    for (int i = 0; i < 2; i++) {
        v[i].x = __expf(v[i].x - mx); v[i].y = __expf(v[i].y - mx);
        v[i].z = __expf(v[i].z - mx); v[i].w = __expf(v[i].w - mx);
        sum += v[i].x + v[i].y + v[i].z + v[i].w;
    }
    #pragma unroll
    for (int o = 16; o > 0; o >>= 1) sum += __shfl_xor_sync(0xffffffffu, sum, o);
    __syncthreads();
    if (lane == 0) red[wid] = sum;
    __syncthreads();
    sum = red[lane & 7];
    #pragma unroll
    for (int o = 4; o > 0; o >>= 1) sum += __shfl_xor_sync(0xffffffffu, sum, o);
    float inv = 1.f / sum;
    #pragma unroll
    for (int i = 0; i < 2; i++) {
        v[i].x *= inv; v[i].y *= inv; v[i].z *= inv; v[i].w *= inv;
        p4[tid + i*256] = v[i];
    }
}

// ---------------- A' = P[b] (168x2048) . X[b] (2048x1024) -> [h][bt][e] ----------------
// block 96x256, warp tile 48x64, 4-stage cp.async, 1 block/SM. grid (KVD/256, 2, B_)
__global__ __launch_bounds__(256, 1) void aprime_kernel(
    const float* __restrict__ P, const float* __restrict__ X,
    float* __restrict__ Ap)
{
    extern __shared__ uint32_t sm[];
    uint32_t sBase = (uint32_t)__cvta_generic_to_shared(sm);

    int tid = threadIdx.x;
    int lane = tid & 31, w = tid >> 5;
    int warpM = w & 1, warpN = w >> 1;
    int lg = lane >> 2, lt = lane & 3;
    int colBase = blockIdx.x * 256;
    int rowBase = blockIdx.y * 96;
    int b = blockIdx.z;

    const float* Ag = P + (size_t)b * TH * M_;
    const float* Bg = X + (size_t)b * M_ * KVD;

    float acc[3][8][4];
    #pragma unroll
    for (int mi = 0; mi < 3; mi++)
        #pragma unroll
        for (int ni = 0; ni < 8; ni++)
            #pragma unroll
            for (int q = 0; q < 4; q++) acc[mi][ni][q] = 0.f;

    auto loadStage = [&](int kc, int buf) {
        int k0 = kc * 32;
        uint32_t base = sBase + (uint32_t)(buf * A2_STAGE) * 4u;
        #pragma unroll
        for (int i = 0; i < 3; i++) {
            int idx = tid + i * 256;
            int r = idx >> 3, c4 = (idx & 7) << 2;
            int gr = rowBase + r;
            int grc = gr < TH ? gr : TH - 1;
            uint32_t sz = gr < TH ? 16u : 0u;
            cpa16(base + ((r*36 + c4) << 2),
                  Ag + (size_t)grc*M_ + k0 + c4, sz);
        }
        uint32_t bb = base + (uint32_t)A2_A_WORDS * 4u;
        #pragma unroll
        for (int i = 0; i < 8; i++) {
            int idx = tid + i * 256;
            int r = idx >> 6, c4 = (idx & 63) << 2;
            cpa16(bb + ((r*AP_B_STRIDE + c4) << 2),
                  Bg + (size_t)(k0 + r)*KVD + colBase + c4, 16u);
        }
        cpa_commit();
    };

    const int NC = M_ / 32;   // 64
    loadStage(0, 0); loadStage(1, 1); loadStage(2, 2);
    for (int kc = 0; kc < NC; kc++) {
        if (kc < NC-2) cpa_wait2();
        else if (kc == NC-2) cpa_wait1(); else cpa_wait0();
        __syncthreads();
        if (kc + 3 < NC) loadStage(kc+3, (kc+3)&3);
        const uint32_t* Ab = sm + (kc&3)*A2_STAGE;
        const uint32_t* Bb = Ab + A2_A_WORDS;
        #pragma unroll
        for (int ks = 0; ks < 4; ks++) {
            int kb = ks * 8;
            uint32_t a[3][4];
            #pragma unroll
            for (int mi = 0; mi < 3; mi++) {
                int r = warpM*48 + mi*16 + lg;
                a[mi][0] = Ab[r*36 + kb + lt];
                a[mi][1] = Ab[(r+8)*36 + kb + lt];
                a[mi][2] = Ab[r*36 + kb + lt + 4];
                a[mi][3] = Ab[(r+8)*36 + kb + lt + 4];
            }
            #pragma unroll
            for (int ni = 0; ni < 8; ni++) {
                int n = warpN*64 + ni*8 + lg;
                uint32_t b0 = Bb[(kb + lt)*AP_B_STRIDE + n];
                uint32_t b1 = Bb[(kb + lt + 4)*AP_B_STRIDE + n];
                mma_tf32(acc[0][ni], a[0], b0, b1);
                mma_tf32(acc[1][ni], a[1], b0, b1);
                mma_tf32(acc[2][ni], a[2], b0, b1);
            }
        }
        __syncthreads();
    }

    #pragma unroll
    for (int mi = 0; mi < 3; mi++) {
        #pragma unroll
        for (int ni = 0; ni < 8; ni++) {
            int cc = colBase + warpN*64 + ni*8 + lt*2;
            #pragma unroll
            for (int half = 0; half < 2; half++) {
                int r = rowBase + warpM*48 + mi*16 + lg + half*8;
                if (r < TH) {
                    int t = r / H_, h = r % H_;
                    int bt = b * T_ + t;
                    float2 v;
                    v.x = acc[mi][ni][half*2 + 0];
                    v.y = acc[mi][ni][half*2 + 1];
                    *(float2*)&Ap[((size_t)h*BT + bt)*KVD + cc] = v;
                }
            }
        }
    }
}

// ---------------- FFN1 split-K: A[448,Kd] x B[Kd,Nc], 64x256 tiles, partials ----------------
// grid (Nc/256, 448/64, 2). Partial s covers K range [s*Kd/2, (s+1)*Kd/2).
__global__ __launch_bounds__(256, 2) void gemm_tc_sk(
    const float* __restrict__ A, const float* __restrict__ Bw,
    float* __restrict__ Cp, int Nc, int Kd)
{
    extern __shared__ uint32_t sm[];
    uint32_t* As = sm;
    uint32_t* Bs = sm + 2*AP_A_WORDS;
    uint32_t sA = (uint32_t)__cvta_generic_to_shared(As);
    uint32_t sB = (uint32_t)__cvta_generic_to_shared(Bs);

    int tid = threadIdx.x;
    int lane = tid & 31, w = tid >> 5;
    int warpM = w & 1, warpN = w >> 1;
    int lg = lane >> 2, lt = lane & 3;
    int colBase = blockIdx.x * 256;
    int rowBase = blockIdx.y * 64;
    int s = blockIdx.z;
    int kOff = s * (Kd >> 1);

    float acc[2][8][4];
    #pragma unroll
    for (int mi = 0; mi < 2; mi++)
        #pragma unroll
        for (int ni = 0; ni < 8; ni++)
            #pragma unroll
            for (int q = 0; q < 4; q++) acc[mi][ni][q] = 0.f;

    auto loadA = [&](int kc, int buf) {
        int k0 = kOff + kc * 32;
        #pragma unroll
        for (int i = 0; i < 2; i++) {
            int idx = tid + i * 256;
            int r = idx >> 3, c4 = (idx & 7) << 2;
            cpa16(sA + ((buf*AP_A_WORDS + r*SC_A_STRIDE + c4) << 2),
                  A + (size_t)(rowBase + r)*Kd + k0 + c4, 16u);
        }
    };
    auto loadB = [&](int kc, int buf) {
        int k0 = kOff + kc * 32;
        #pragma unroll
        for (int i = 0; i < 8; i++) {
            int idx = tid + i * 256;
            int r = idx >> 6, c4 = (idx & 63) << 2;
            cpa16(sB + ((buf*AP_B_WORDS + r*AP_B_STRIDE + c4) << 2),
                  Bw + (size_t)(k0 + r)*Nc + colBase + c4, 16u);
        }
    };

    const int NC = (Kd >> 1) / 32;
    loadA(0, 0); loadB(0, 0); cpa_commit();
    for (int kc = 0; kc < NC; kc++) {
        int cur = kc & 1;
        if (kc + 1 < NC) {
            loadA(kc+1, cur^1); loadB(kc+1, cur^1); cpa_commit();
            cpa_wait1();
        } else {
            cpa_wait0();
        }
        __syncthreads();
        const uint32_t* Ab = As + cur*AP_A_WORDS;
        const uint32_t* Bb = Bs + cur*AP_B_WORDS;
        #pragma unroll
        for (int ks = 0; ks < 4; ks++) {
            int kb = ks * 8;
            uint32_t a[2][4];
            #pragma unroll
            for (int mi = 0; mi < 2; mi++) {
                int r = warpM*32 + mi*16 + lg;
                a[mi][0] = Ab[r*SC_A_STRIDE + kb + lt];
                a[mi][1] = Ab[(r+8)*SC_A_STRIDE + kb + lt];
                a[mi][2] = Ab[r*SC_A_STRIDE + kb + lt + 4];
                a[mi][3] = Ab[(r+8)*SC_A_STRIDE + kb + lt + 4];
            }
            #pragma unroll
            for (int ni = 0; ni < 8; ni++) {
                int n = warpN*64 + ni*8 + lg;
                uint32_t b0 = Bb[(kb + lt)*AP_B_STRIDE + n];
                uint32_t b1 = Bb[(kb + lt + 4)*AP_B_STRIDE + n];
                mma_tf32(acc[0][ni], a[0], b0, b1);
                mma_tf32(acc[1][ni], a[1], b0, b1);
            }
        }
        __syncthreads();
    }

    float* Cs = Cp + (size_t)s * BT * Nc;
    #pragma unroll
    for (int mi = 0; mi < 2; mi++) {
        #pragma unroll
        for (int ni = 0; ni < 8; ni++) {
            int cc = colBase + warpN*64 + ni*8 + lt*2;
            #pragma unroll
            for (int half = 0; half < 2; half++) {
                int r = rowBase + warpM*32 + mi*16 + lg + half*8;
                float2 v;
                v.x = acc[mi][ni][half*2 + 0];
                v.y = acc[mi][ni][half*2 + 1];
                *(float2*)&Cs[(size_t)r*Nc + cc] = v;
            }
        }
    }
}

// ---------------- FFN2 split-K: 64x64 tiles. grid (Nc/64, 448/64, 2) ----------------
__global__ __launch_bounds__(256) void gemm_n64_sk(
    const float* __restrict__ A, const float* __restrict__ Bw,
    float* __restrict__ Cp, int Nc, int Kd)
{
    __shared__ uint32_t As[2][64][36];
    __shared__ uint32_t Bs[2][32][72];
    uint32_t sA = (uint32_t)__cvta_generic_to_shared(&As[0][0][0]);
    uint32_t sB = (uint32_t)__cvta_generic_to_shared(&Bs[0][0][0]);

    int tid = threadIdx.x;
    int lane = tid & 31, w = tid >> 5;
    int warpM = w & 1, warpN = w >> 1;
    int lg = lane >> 2, lt = lane & 3;
    int colBase = blockIdx.x * 64;
    int rowBase = blockIdx.y * 64;
    int s = blockIdx.z;
    int kOff = s * (Kd >> 1);

    float acc[2][2][4];
    #pragma unroll
    for (int mi = 0; mi < 2; mi++)
        #pragma unroll
        for (int ni = 0; ni < 2; ni++)
            #pragma unroll
            for (int q = 0; q < 4; q++) acc[mi][ni][q] = 0.f;

    auto loadStage = [&](int kc, int buf) {
        int k0 = kOff + kc * 32;
        #pragma unroll
        for (int i = 0; i < 2; i++) {
            int idx = tid + i * 256;
            int r = idx >> 3, c4 = (idx & 7) << 2;
            cpa16(sA + ((buf*64*36 + r*36 + c4) << 2),
                  A + (size_t)(rowBase + r)*Kd + k0 + c4, 16u);
        }
        #pragma unroll
        for (int i = 0; i < 2; i++) {
            int idx = tid + i * 256;
            int r = idx >> 4, c4 = (idx & 15) << 2;
            cpa16(sB + ((buf*32*72 + r*72 + c4) << 2),
                  Bw + (size_t)(k0 + r)*Nc + colBase + c4, 16u);
        }
        cpa_commit();
    };

    const int NC = (Kd >> 1) / 32;
    loadStage(0, 0);
    for (int kc = 0; kc < NC; kc++) {
        int cur = kc & 1;
        if (kc + 1 < NC) { loadStage(kc+1, cur^1); cpa_wait1(); }
        else             { cpa_wait0(); }
        __syncthreads();
        #pragma unroll
        for (int ks = 0; ks < 4; ks++) {
            int kb = ks * 8;
            uint32_t a[2][4];
            #pragma unroll
            for (int mi = 0; mi < 2; mi++) {
                int r = warpM*32 + mi*16 + lg;
                a[mi][0] = As[cur][r][kb + lt];
                a[mi][1] = As[cur][r+8][kb + lt];
                a[mi][2] = As[cur][r][kb + lt + 4];
                a[mi][3] = As[cur][r+8][kb + lt + 4];
            }
            #pragma unroll
            for (int ni = 0; ni < 2; ni++) {
                int n = warpN*16 + ni*8 + lg;
                uint32_t b0 = Bs[cur][kb + lt][n];
                uint32_t b1 = Bs[cur][kb + lt + 4][n];
                mma_tf32(acc[0][ni], a[0], b0, b1);
                mma_tf32(acc[1][ni], a[1], b0, b1);
            }
        }
        __syncthreads();
    }

    float* Cs = Cp + (size_t)s * BT * Nc;
    #pragma unroll
    for (int mi = 0; mi < 2; mi++) {
        #pragma unroll
        for (int ni = 0; ni < 2; ni++) {
            int cc = colBase + warpN*16 + ni*8 + lt*2;
            #pragma unroll
            for (int half = 0; half < 2; half++) {
                int r = rowBase + warpM*32 + mi*16 + lg + half*8;
                float2 v;
                v.x = acc[mi][ni][half*2 + 0];
                v.y = acc[mi][ni][half*2 + 1];
                *(float2*)&Cs[(size_t)r*Nc + cc] = v;
            }
        }
    }
}

// ---------------- split-K reduce: C = p[0] + p[1] + bias (+ReLU) ----------------
template<bool RELU>
__global__ __launch_bounds__(256) void reduce_sk_kernel(
    const float* __restrict__ p, const float* __restrict__ bias,
    float* __restrict__ C, int Nc)
{
    int r = blockIdx.x;
    const float4* p0 = (const float4*)(p + (size_t)r * Nc);
    const float4* p1 = (const float4*)(p + (size_t)(BT + r) * Nc);
    const float4* b4 = (const float4*)bias;
    float4* c4 = (float4*)(C + (size_t)r * Nc);
    for (int i = threadIdx.x; i < (Nc >> 2); i += 256) {
        float4 a = p0[i], b = p1[i], bi = b4[i];
        float4 v;
        v.x = a.x + b.x + bi.x; v.y = a.y + b.y + bi.y;
        v.z = a.z + b.z + bi.z; v.w = a.w + b.w + bi.w;
        if (RELU) {
            v.x = fmaxf(v.x, 0.f); v.y = fmaxf(v.y, 0.f);
            v.z = fmaxf(v.z, 0.f); v.w = fmaxf(v.w, 0.f);
        }
        c4[i] = v;
    }
}

// ---------------- attn_out = A'[h] . WV_h + bV_h via mma (64x64 tiles/head) ----------------
// grid (448/64, H_). A = Ap + h*BT*KVD (ld KVD); B rows: WV[k*QD + h*64 + c].
__global__ __launch_bounds__(256) void attnout_mma_kernel(
    const float* __restrict__ Ap, const float* __restrict__ WV,
    const float* __restrict__ bV, float* __restrict__ O)
{
    __shared__ uint32_t As[2][64][36];
    __shared__ uint32_t Bs[2][32][72];
    uint32_t sA = (uint32_t)__cvta_generic_to_shared(&As[0][0][0]);
    uint32_t sB = (uint32_t)__cvta_generic_to_shared(&Bs[0][0][0]);

    int tid = threadIdx.x;
    int lane = tid & 31, w = tid >> 5;
    int warpM = w & 1, warpN = w >> 1;
    int lg = lane >> 2, lt = lane & 3;
    int rowBase = blockIdx.x * 64;
    int h = blockIdx.y;

    const float* Ag = Ap + (size_t)h * BT * KVD;
    const float* Bg = WV + h * HD_;

    float acc[2][2][4];
    #pragma unroll
    for (int mi = 0; mi < 2; mi++)
        #pragma unroll
        for (int ni = 0; ni < 2; ni++)
            #pragma unroll
            for (int q = 0; q < 4; q++) acc[mi][ni][q] = 0.f;

    auto loadStage = [&](int kc, int buf) {
        int k0 = kc * 32;
        #pragma unroll
        for (int i = 0; i < 2; i++) {
            int idx = tid + i * 256;
            int r = idx >> 3, c4 = (idx & 7) << 2;
            cpa16(sA + ((buf*64*36 + r*36 + c4) << 2),
                  Ag + (size_t)(rowBase + r)*KVD + k0 + c4, 16u);
        }
        #pragma unroll
        for (int i = 0; i < 2; i++) {
            int idx = tid + i * 256;
            int r = idx >> 4, c4 = (idx & 15) << 2;
            cpa16(sB + ((buf*32*72 + r*72 + c4) << 2),
                  Bg + (size_t)(k0 + r)*QD + c4, 16u);
        }
        cpa_commit();
    };

    const int NC = KVD / 32;
    loadStage(0, 0);
    for (int kc = 0; kc < NC; kc++) {
        int cur = kc & 1;
        if (kc + 1 < NC) { loadStage(kc+1, cur^1); cpa_wait1(); }
        else             { cpa_wait0(); }
        __syncthreads();
        #pragma unroll
        for (int ks = 0; ks < 4; ks++) {
            int kb = ks * 8;
            uint32_t a[2][4];
            #pragma unroll
            for (int mi = 0; mi < 2; mi++) {
                int r = warpM*32 + mi*16 + lg;
                a[mi][0] = As[cur][r][kb + lt];
                a[mi][1] = As[cur][r+8][kb + lt];
                a[mi][2] = As[cur][r][kb + lt + 4];
                a[mi][3] = As[cur][r+8][kb + lt + 4];
            }
            #pragma unroll
            for (int ni = 0; ni < 2; ni++) {
                int n = warpN*16 + ni*8 + lg;
                uint32_t b0 = Bs[cur][kb + lt][n];
                uint32_t b1 = Bs[cur][kb + lt + 4][n];
                mma_tf32(acc[0][ni], a[0], b0, b1);
                mma_tf32(acc[1][ni], a[1], b0, b1);
            }
        }
        __syncthreads();
    }

    #pragma unroll
    for (int mi = 0; mi < 2; mi++) {
        #pragma unroll
        for (int ni = 0; ni < 2; ni++) {
            int cc = warpN*16 + ni*8 + lt*2;
            float bi0 = bV[h*HD_ + cc], bi1 = bV[h*HD_ + cc + 1];
            #pragma unroll
            for (int half = 0; half < 2; half++) {
                int r = rowBase + warpM*32 + mi*16 + lg + half*8;
                float2 v;
                v.x = acc[mi][ni][half*2 + 0] + bi0;
                v.y = acc[mi][ni][half*2 + 1] + bi1;
                *(float2*)&O[(size_t)r*QD + h*HD_ + cc] = v;
            }
        }
    }
}

// ---------------- residual add + LayerNorm ----------------
__global__ __launch_bounds__(256) void add_ln_kernel(
    const float* __restrict__ A, const float* __restrict__ Bv,
    const float* __restrict__ g, const float* __restrict__ be,
    float* __restrict__ out)
{
    __shared__ float xs[QD];
    __shared__ float red[256];
    int r = blockIdx.x, tid = threadIdx.x;
    float lsum = 0.f;
    for (int i = tid; i < QD; i += 256) {
        float v = A[(size_t)r*QD + i] + Bv[(size_t)r*QD + i];
        xs[i] = v;
        lsum += v;
    }
    red[tid] = lsum; __syncthreads();
    for (int s = 128; s > 0; s >>= 1) {
        if (tid < s) red[tid] += red[tid + s];
        __syncthreads();
    }
    float mu = red[0] / QD; __syncthreads();
    float lv = 0.f;
    for (int i = tid; i < QD; i += 256) {
        float d0 = xs[i] - mu;
        lv += d0 * d0;
    }
    red[tid] = lv; __syncthreads();
    for (int s = 128; s > 0; s >>= 1) {
        if (tid < s) red[tid] += red[tid + s];
        __syncthreads();
    }
    float inv = rsqrtf(red[0] / QD + EPS_); __syncthreads();
    for (int i = tid; i < QD; i += 256)
        out[(size_t)r*QD + i] = (xs[i] - mu) * inv * g[i] + be[i];
}

// ---------------- launch ----------------
extern "C" void kernel_launch(void* const* d_in, const int* in_sizes, int n_in,
                              void* d_out, int out_size)
{
    const float* X   = (const float*)d_in[0];
    const float* KV  = (const float*)d_in[1];
    const float* WQ  = (const float*)d_in[2];
    const float* bQ  = (const float*)d_in[3];
    const float* WK  = (const float*)d_in[4];
    const float* bK  = (const float*)d_in[5];
    const float* WV  = (const float*)d_in[6];
    const float* bV  = (const float*)d_in[7];
    const float* W1  = (const float*)d_in[8];
    const float* b1  = (const float*)d_in[9];
    const float* W2  = (const float*)d_in[10];
    const float* b2  = (const float*)d_in[11];
    const float* g1  = (const float*)d_in[12];
    const float* be1 = (const float*)d_in[13];
    const float* g2  = (const float*)d_in[14];
    const float* be2 = (const float*)d_in[15];

    float* out   = (float*)d_out;
    float* attnw = out + (size_t)BT*QD;

    float *Qp, *Qtp, *cp, *Sp, *App, *Aop, *X1, *Hm, *Fp, *P1, *P2;
    cudaGetSymbolAddress((void**)&Qp,  g_Q);
    cudaGetSymbolAddress((void**)&Qtp, g_Qt);
    cudaGetSymbolAddress((void**)&cp,  g_c);
    cudaGetSymbolAddress((void**)&Sp,  g_S);
    cudaGetSymbolAddress((void**)&App, g_Ap);
    cudaGetSymbolAddress((void**)&Aop, g_attn);
    cudaGetSymbolAddress((void**)&X1,  g_x1);
    cudaGetSymbolAddress((void**)&Hm,  g_h);
    cudaGetSymbolAddress((void**)&Fp,  g_ff);
    cudaGetSymbolAddress((void**)&P1,  g_p1);
    cudaGetSymbolAddress((void**)&P2,  g_p2);

    cudaFuncSetAttribute(scores_kernel, cudaFuncAttributeMaxDynamicSharedMemorySize, SC_SMEM_BYTES);
    cudaFuncSetAttribute(aprime_kernel, cudaFuncAttributeMaxDynamicSharedMemorySize, A2_SMEM_BYTES);
    cudaFuncSetAttribute(gemm_tc_sk,    cudaFuncAttributeMaxDynamicSharedMemorySize, AP_SMEM_BYTES);

    // Q projection (one GEMM per expert token)
    qproj_kernel<<<dim3(T_, QD/128), 256>>>(X, WQ, bQ, Qp);

    // Qt = Q . WK^T (per head), c = Q . bK
    qt_kernel<<<dim3(H_, BT/64, KVD/64), 256>>>(Qp, WK, Qtp);
    crow_kernel<<<dim3(BT, H_), 32>>>(Qp, bK, cp);

    // scores = Qt . X^T  (64x256 tiles, 2-stage, 2 blk/SM)
    scores_kernel<<<dim3(M_/256, 3, B_), 256, SC_SMEM_BYTES>>>(Qtp, KV, Sp);

    // attn_w = softmax((scores + c)/8) -> written directly to output
    softmax_kernel<<<B_*TH, 256>>>(Sp, cp, attnw);

    // A' = P . X  (96x256 tiles, 4-stage)
    aprime_kernel<<<dim3(KVD/256, 2, B_), 256, A2_SMEM_BYTES>>>(attnw, KV, App);

    // attn_out = A' . WV + bV  (mma, per-head 64x64 tiles)
    attnout_mma_kernel<<<dim3(BT/64, H_), 256>>>(App, WV, bV, Aop);

    // x1 = LN(tokens + attn_out)
    add_ln_kernel<<<BT, 256>>>(X, Aop, g1, be1, X1);

    // FFN1: split-K x2 + reduce(ReLU+bias)
    gemm_tc_sk<<<dim3(FF_/256, BT/64, 2), 256, AP_SMEM_BYTES>>>(X1, W1, P1, FF_, QD);
    reduce_sk_kernel<true><<<BT, 256>>>(P1, b1, Hm, FF_);

    // FFN2: split-K x2 (64x64 tiles) + reduce(bias)
    gemm_n64_sk<<<dim3(QD/64, BT/64, 2), 256>>>(Hm, W2, P2, QD, FF_);
    reduce_sk_kernel<false><<<BT, 256>>>(P2, b2, Fp, QD);

    // out = LN(x1 + ff)
    add_ln_kernel<<<BT, 256>>>(X1, Fp, g2, be2, out);
}

// round 15
// speedup vs baseline: 1.5259x; 1.5259x over previous
#include <cuda_runtime.h>
#include <cstdint>
#include <cstddef>

#define B_   32
#define T_   14
#define M_   2048
#define QD   768
#define KVD  1024
#define H_   12
#define HD_  64
#define FF_  3072
#define BT   (B_*T_)      // 448
#define TH   (T_*H_)      // 168
#define EPS_ 1e-5f

// ---------------- scratch (device globals; no allocation allowed) ----------------
__device__ float g_Q[BT*QD];
__device__ float g_Qt[(size_t)B_*TH*KVD];       // 22 MB
__device__ float g_c[B_*TH];
__device__ float g_S[(size_t)B_*TH*M_];         // 44 MB
__device__ float g_Ap[(size_t)H_*BT*KVD];       // 22 MB
__device__ float g_attn[BT*QD];
__device__ float g_x1[BT*QD];
__device__ float g_h[BT*FF_];
__device__ float g_ff[BT*QD];
__device__ float g_p1[2*(size_t)BT*FF_];        // FFN1 split-K partials
__device__ float g_p2[2*(size_t)BT*QD];         // FFN2 split-K partials

// ---------------- helpers ----------------
__device__ __forceinline__ void mma_tf32(float* c, const uint32_t* a, uint32_t b0, uint32_t b1) {
    asm volatile(
        "mma.sync.aligned.m16n8k8.row.col.f32.tf32.tf32.f32 "
        "{%0,%1,%2,%3}, {%4,%5,%6,%7}, {%8,%9}, {%0,%1,%2,%3};\n"
        : "+f"(c[0]), "+f"(c[1]), "+f"(c[2]), "+f"(c[3])
        : "r"(a[0]), "r"(a[1]), "r"(a[2]), "r"(a[3]), "r"(b0), "r"(b1));
}

__device__ __forceinline__ void cpa16(uint32_t saddr, const void* g, uint32_t sz) {
    asm volatile("cp.async.cg.shared.global [%0], [%1], 16, %2;"
                 :: "r"(saddr), "l"(g), "r"(sz));
}
__device__ __forceinline__ void cpa_commit() { asm volatile("cp.async.commit_group;"); }
__device__ __forceinline__ void cpa_wait2()  { asm volatile("cp.async.wait_group 2;"); }
__device__ __forceinline__ void cpa_wait1()  { asm volatile("cp.async.wait_group 1;"); }
__device__ __forceinline__ void cpa_wait0()  { asm volatile("cp.async.wait_group 0;"); }

// ---- smem layouts (uint32 words) ----
#define SC_A_STRIDE 36
#define AP_B_STRIDE 264
#define AP_A_WORDS  (64*SC_A_STRIDE)
#define AP_B_WORDS  (32*AP_B_STRIDE)
#define AP_SMEM_BYTES ((2*AP_A_WORDS + 2*AP_B_WORDS)*4)    // 86016

// 96x256 4-stage layouts (scores B is K-contig rows: stride 36; aprime B is N-contig: stride 264)
#define S2_A_WORDS   (96*36)
#define S2_B_WORDS   (256*36)
#define S2_STAGE     (S2_A_WORDS + S2_B_WORDS)
#define S2_SMEM_BYTES (4*S2_STAGE*4)         // 202752

#define A2_A_WORDS   (96*36)
#define A2_B_WORDS   (32*AP_B_STRIDE)
#define A2_STAGE     (A2_A_WORDS + A2_B_WORDS)
#define A2_SMEM_BYTES (4*A2_STAGE*4)         // 190464

// ---------------- Q projection: one GEMM per expert-token t ----------------
__global__ __launch_bounds__(256) void qproj_kernel(
    const float* __restrict__ X, const float* __restrict__ WQ,
    const float* __restrict__ bQ, float* __restrict__ Q)
{
    int t = blockIdx.x;
    int colBase = blockIdx.y * 128;
    __shared__ float As[32][33];
    __shared__ float Bs[32][132];
    int tid = threadIdx.x;
    int r0 = (tid >> 5) * 4;
    int c0 = (tid & 31) * 4;
    float acc[4][4];
    #pragma unroll
    for (int i = 0; i < 4; i++)
        #pragma unroll
        for (int j = 0; j < 4; j++) acc[i][j] = 0.f;

    const float* Wt = WQ + (size_t)t * QD * QD;
    for (int k0 = 0; k0 < QD; k0 += 32) {
        {
            int r = tid >> 3, c4 = (tid & 7) << 2;
            float4 v = *(const float4*)&X[(size_t)(r*T_ + t)*QD + k0 + c4];
            As[r][c4+0] = v.x; As[r][c4+1] = v.y; As[r][c4+2] = v.z; As[r][c4+3] = v.w;
        }
        #pragma unroll
        for (int i = 0; i < 4; i++) {
            int idx = tid + i * 256;
            int r = idx >> 5, c4 = (idx & 31) << 2;
            float4 v = *(const float4*)&Wt[(size_t)(k0 + r)*QD + colBase + c4];
            Bs[r][c4+0] = v.x; Bs[r][c4+1] = v.y; Bs[r][c4+2] = v.z; Bs[r][c4+3] = v.w;
        }
        __syncthreads();
        #pragma unroll
        for (int kk = 0; kk < 32; kk++) {
            float a[4];
            #pragma unroll
            for (int i = 0; i < 4; i++) a[i] = As[r0+i][kk];
            float4 b4 = *(float4*)&Bs[kk][c0];
            float bb[4] = {b4.x, b4.y, b4.z, b4.w};
            #pragma unroll
            for (int i = 0; i < 4; i++)
                #pragma unroll
                for (int j = 0; j < 4; j++) acc[i][j] += a[i]*bb[j];
        }
        __syncthreads();
    }
    #pragma unroll
    for (int i = 0; i < 4; i++) {
        int bt = (r0 + i)*T_ + t;
        #pragma unroll
        for (int j = 0; j < 4; j++) {
            int c = colBase + c0 + j;
            Q[(size_t)bt*QD + c] = acc[i][j] + bQ[t*QD + c];
        }
    }
}

// ---------------- Qt[b,t,h,e] = sum_d Q[bt, h*64+d] * WK[e, h*64+d] ----------------
__global__ __launch_bounds__(256) void qt_kernel(
    const float* __restrict__ Q, const float* __restrict__ WK,
    float* __restrict__ Qt)
{
    int h  = blockIdx.x;
    int rt = blockIdx.y;
    int et = blockIdx.z;
    __shared__ float Asq[64][65];
    __shared__ float Bsq[64][65];
    int tid = threadIdx.x;
    #pragma unroll
    for (int it = 0; it < 4; it++) {
        int id = tid + it * 256;
        int r = id >> 4, c4 = (id & 15) << 2;
        float4 v = *(const float4*)&Q[(size_t)(rt*64 + r)*QD + h*HD_ + c4];
        Asq[r][c4+0] = v.x; Asq[r][c4+1] = v.y; Asq[r][c4+2] = v.z; Asq[r][c4+3] = v.w;
        float4 w = *(const float4*)&WK[(size_t)(et*64 + r)*QD + h*HD_ + c4];
        Bsq[r][c4+0] = w.x; Bsq[r][c4+1] = w.y; Bsq[r][c4+2] = w.z; Bsq[r][c4+3] = w.w;
    }
    __syncthreads();
    int r0 = (tid >> 4) * 4, e0 = (tid & 15) * 4;
    float acc[4][4];
    #pragma unroll
    for (int i = 0; i < 4; i++)
        #pragma unroll
        for (int j = 0; j < 4; j++) acc[i][j] = 0.f;
    #pragma unroll 8
    for (int d = 0; d < 64; d++) {
        float a[4], b[4];
        #pragma unroll
        for (int i = 0; i < 4; i++) a[i] = Asq[r0+i][d];
        #pragma unroll
        for (int j = 0; j < 4; j++) b[j] = Bsq[e0+j][d];
        #pragma unroll
        for (int i = 0; i < 4; i++)
            #pragma unroll
            for (int j = 0; j < 4; j++) acc[i][j] += a[i]*b[j];
    }
    #pragma unroll
    for (int i = 0; i < 4; i++) {
        int bt = rt*64 + r0 + i;
        int b  = bt / T_, t = bt % T_;
        float* dst = Qt + ((size_t)(b*TH + t*H_ + h))*KVD + et*64 + e0;
        #pragma unroll
        for (int j = 0; j < 4; j++) dst[j] = acc[i][j];
    }
}

// ---------------- c row constant ----------------
__global__ __launch_bounds__(32) void crow_kernel(
    const float* __restrict__ Q, const float* __restrict__ bK, float* __restrict__ c)
{
    int bt = blockIdx.x, h = blockIdx.y;
    int lane = threadIdx.x;
    float s = Q[(size_t)bt*QD + h*HD_ + lane]      * bK[h*HD_ + lane]
            + Q[(size_t)bt*QD + h*HD_ + 32 + lane] * bK[h*HD_ + 32 + lane];
    #pragma unroll
    for (int o = 16; o > 0; o >>= 1) s += __shfl_down_sync(0xffffffffu, s, o);
    if (lane == 0) {
        int b = bt / T_, t = bt % T_;
        c[b*TH + t*H_ + h] = s;
    }
}

// ---------------- scores: S[b] = Qt[b] (168x1024) . X[b]^T -> [168, 2048] ----------------
// block 96x256, warp tile 48x64 (2M x 4N warps), 4-stage cp.async, 1 block/SM.
// grid (M_/256, 2, B_)
__global__ __launch_bounds__(256, 1) void scores_kernel(
    const float* __restrict__ Qt, const float* __restrict__ X,
    float* __restrict__ S)
{
    extern __shared__ uint32_t sm[];
    uint32_t sBase = (uint32_t)__cvta_generic_to_shared(sm);

    int tid = threadIdx.x;
    int lane = tid & 31, w = tid >> 5;
    int warpM = w & 1, warpN = w >> 1;
    int lg = lane >> 2, lt = lane & 3;
    int colBase = blockIdx.x * 256;
    int rowBase = blockIdx.y * 96;
    int b = blockIdx.z;

    const float* Ag = Qt + (size_t)b * TH * KVD;
    const float* Bg = X  + (size_t)b * M_ * KVD;

    float acc[3][8][4];
    #pragma unroll
    for (int mi = 0; mi < 3; mi++)
        #pragma unroll
        for (int ni = 0; ni < 8; ni++)
            #pragma unroll
            for (int q = 0; q < 4; q++) acc[mi][ni][q] = 0.f;

    auto loadStage = [&](int kc, int buf) {
        int k0 = kc * 32;
        uint32_t base = sBase + (uint32_t)(buf * S2_STAGE) * 4u;
        #pragma unroll
        for (int i = 0; i < 3; i++) {
            int idx = tid + i * 256;
            int r = idx >> 3, c4 = (idx & 7) << 2;
            int gr = rowBase + r;
            int grc = gr < TH ? gr : TH - 1;
            uint32_t sz = gr < TH ? 16u : 0u;
            cpa16(base + ((r*36 + c4) << 2),
                  Ag + (size_t)grc*KVD + k0 + c4, sz);
        }
        uint32_t bb = base + (uint32_t)S2_A_WORDS * 4u;
        #pragma unroll
        for (int i = 0; i < 8; i++) {
            int idx = tid + i * 256;
            int r = idx >> 3, c4 = (idx & 7) << 2;
            cpa16(bb + ((r*36 + c4) << 2),
                  Bg + (size_t)(colBase + r)*KVD + k0 + c4, 16u);
        }
        cpa_commit();
    };

    const int NC = KVD / 32;   // 32
    loadStage(0, 0); loadStage(1, 1); loadStage(2, 2);
    for (int kc = 0; kc < NC; kc++) {
        if (kc < NC-2) cpa_wait2(); else if (kc == NC-2) cpa_wait1(); else cpa_wait0();
        __syncthreads();
        if (kc + 3 < NC) loadStage(kc+3, (kc+3)&3);
        const uint32_t* Ab = sm + (kc&3)*S2_STAGE;
        const uint32_t* Bb = Ab + S2_A_WORDS;
        #pragma unroll
        for (int ks = 0; ks < 4; ks++) {
            int kb = ks * 8;
            uint32_t a[3][4];
            #pragma unroll
            for (int mi = 0; mi < 3; mi++) {
                int r = warpM*48 + mi*16 + lg;
                a[mi][0] = Ab[r*36 + kb + lt];
                a[mi][1] = Ab[(r+8)*36 + kb + lt];
                a[mi][2] = Ab[r*36 + kb + lt + 4];
                a[mi][3] = Ab[(r+8)*36 + kb + lt + 4];
            }
            #pragma unroll
            for (int ni = 0; ni < 8; ni++) {
                int n = warpN*64 + ni*8 + lg;
                uint32_t b0 = Bb[n*36 + kb + lt];
                uint32_t b1 = Bb[n*36 + kb + lt + 4];
                mma_tf32(acc[0][ni], a[0], b0, b1);
                mma_tf32(acc[1][ni], a[1], b0, b1);
                mma_tf32(acc[2][ni], a[2], b0, b1);
            }
        }
        __syncthreads();
    }

    float* Sg = S + (size_t)b * TH * M_;
    #pragma unroll
    for (int mi = 0; mi < 3; mi++) {
        #pragma unroll
        for (int ni = 0; ni < 8; ni++) {
            int r = rowBase + warpM*48 + mi*16 + lg;
            int cc = colBase + warpN*64 + ni*8 + lt*2;
            if (r < TH) {
                float2 v; v.x = acc[mi][ni][0]; v.y = acc[mi][ni][1];
                *(float2*)&Sg[(size_t)r*M_ + cc] = v;
            }
            if (r + 8 < TH) {
                float2 v; v.x = acc[mi][ni][2]; v.y = acc[mi][ni][3];
                *(float2*)&Sg[(size_t)(r+8)*M_ + cc] = v;
            }
        }
    }
}

// ---------------- softmax (vectorized float4, shuffle reductions) ----------------
__global__ __launch_bounds__(256) void softmax_kernel(
    const float* __restrict__ S, const float* __restrict__ c,
    float* __restrict__ P)
{
    __shared__ float red[8];
    int row = blockIdx.x, tid = threadIdx.x;
    int lane = tid & 31, wid = tid >> 5;
    const float4* s4 = (const float4*)(S + (size_t)row * M_);
    float4*       p4 = (float4*)(P + (size_t)row * M_);
    float cv = c[row];

    float4 v[2];
    float mx = -1e30f;
    #pragma unroll
    for (int i = 0; i < 2; i++) {
        float4 t = s4[tid + i*256];
        t.x = (t.x + cv) * 0.125f; t.y = (t.y + cv) * 0.125f;
        t.z = (t.z + cv) * 0.125f; t.w = (t.w + cv) * 0.125f;
        v[i] = t;
        mx = fmaxf(mx, fmaxf(fmaxf(t.x, t.y), fmaxf(t.z, t.w)));
    }
    #pragma unroll
    for (int o = 16; o > 0; o >>= 1) mx = fmaxf(mx, __shfl_xor_sync(0xffffffffu, mx, o));
    if (lane == 0) red[wid] = mx;
    __syncthreads();
    mx = red[lane & 7];
    #pragma unroll
    for (int o = 4; o > 0; o >>= 1) mx = fmaxf(mx, __shfl_xor_sync(0xffffffffu, mx, o));

    float sum = 0.f;
    #pragma unroll
    for (int i = 0; i < 2; i++) {
        v[i].x = __expf(v[i].x - mx); v[i].y = __expf(v[i].y - mx);
        v[i].z = __expf(v[i].z - mx); v[i].w = __expf(v[i].w - mx);
        sum += v[i].x + v[i].y + v[i].z + v[i].w;
    }
    #pragma unroll
    for (int o = 16; o > 0; o >>= 1) sum += __shfl_xor_sync(0xffffffffu, sum, o);
    __syncthreads();
    if (lane == 0) red[wid] = sum;
    __syncthreads();
    sum = red[lane & 7];
    #pragma unroll
    for (int o = 4; o > 0; o >>= 1) sum += __shfl_xor_sync(0xffffffffu, sum, o);
    float inv = 1.f / sum;
    #pragma unroll
    for (int i = 0; i < 2; i++) {
        v[i].x *= inv; v[i].y *= inv; v[i].z *= inv; v[i].w *= inv;
        p4[tid + i*256] = v[i];
    }
}

// ---------------- A' = P[b] (168x2048) . X[b] (2048x1024) -> [h][bt][e] ----------------
// block 96x256, warp tile 48x64, 4-stage cp.async, 1 block/SM. grid (KVD/256, 2, B_)
__global__ __launch_bounds__(256, 1) void aprime_kernel(
    const float* __restrict__ P, const float* __restrict__ X,
    float* __restrict__ Ap)
{
    extern __shared__ uint32_t sm[];
    uint32_t sBase = (uint32_t)__cvta_generic_to_shared(sm);

    int tid = threadIdx.x;
    int lane = tid & 31, w = tid >> 5;
    int warpM = w & 1, warpN = w >> 1;
    int lg = lane >> 2, lt = lane & 3;
    int colBase = blockIdx.x * 256;
    int rowBase = blockIdx.y * 96;
    int b = blockIdx.z;

    const float* Ag = P + (size_t)b * TH * M_;
    const float* Bg = X + (size_t)b * M_ * KVD;

    float acc[3][8][4];
    #pragma unroll
    for (int mi = 0; mi < 3; mi++)
        #pragma unroll
        for (int ni = 0; ni < 8; ni++)
            #pragma unroll
            for (int q = 0; q < 4; q++) acc[mi][ni][q] = 0.f;

    auto loadStage = [&](int kc, int buf) {
        int k0 = kc * 32;
        uint32_t base = sBase + (uint32_t)(buf * A2_STAGE) * 4u;
        #pragma unroll
        for (int i = 0; i < 3; i++) {
            int idx = tid + i * 256;
            int r = idx >> 3, c4 = (idx & 7) << 2;
            int gr = rowBase + r;
            int grc = gr < TH ? gr : TH - 1;
            uint32_t sz = gr < TH ? 16u : 0u;
            cpa16(base + ((r*36 + c4) << 2),
                  Ag + (size_t)grc*M_ + k0 + c4, sz);
        }
        uint32_t bb = base + (uint32_t)A2_A_WORDS * 4u;
        #pragma unroll
        for (int i = 0; i < 8; i++) {
            int idx = tid + i * 256;
            int r = idx >> 6, c4 = (idx & 63) << 2;
            cpa16(bb + ((r*AP_B_STRIDE + c4) << 2),
                  Bg + (size_t)(k0 + r)*KVD + colBase + c4, 16u);
        }
        cpa_commit();
    };

    const int NC = M_ / 32;   // 64
    loadStage(0, 0); loadStage(1, 1); loadStage(2, 2);
    for (int kc = 0; kc < NC; kc++) {
        if (kc < NC-2) cpa_wait2();
        else if (kc == NC-2) cpa_wait1(); else cpa_wait0();
        __syncthreads();
        if (kc + 3 < NC) loadStage(kc+3, (kc+3)&3);
        const uint32_t* Ab = sm + (kc&3)*A2_STAGE;
        const uint32_t* Bb = Ab + A2_A_WORDS;
        #pragma unroll
        for (int ks = 0; ks < 4; ks++) {
            int kb = ks * 8;
            uint32_t a[3][4];
            #pragma unroll
            for (int mi = 0; mi < 3; mi++) {
                int r = warpM*48 + mi*16 + lg;
                a[mi][0] = Ab[r*36 + kb + lt];
                a[mi][1] = Ab[(r+8)*36 + kb + lt];
                a[mi][2] = Ab[r*36 + kb + lt + 4];
                a[mi][3] = Ab[(r+8)*36 + kb + lt + 4];
            }
            #pragma unroll
            for (int ni = 0; ni < 8; ni++) {
                int n = warpN*64 + ni*8 + lg;
                uint32_t b0 = Bb[(kb + lt)*AP_B_STRIDE + n];
                uint32_t b1 = Bb[(kb + lt + 4)*AP_B_STRIDE + n];
                mma_tf32(acc[0][ni], a[0], b0, b1);
                mma_tf32(acc[1][ni], a[1], b0, b1);
                mma_tf32(acc[2][ni], a[2], b0, b1);
            }
        }
        __syncthreads();
    }

    #pragma unroll
    for (int mi = 0; mi < 3; mi++) {
        #pragma unroll
        for (int ni = 0; ni < 8; ni++) {
            int cc = colBase + warpN*64 + ni*8 + lt*2;
            #pragma unroll
            for (int half = 0; half < 2; half++) {
                int r = rowBase + warpM*48 + mi*16 + lg + half*8;
                if (r < TH) {
                    int t = r / H_, h = r % H_;
                    int bt = b * T_ + t;
                    float2 v;
                    v.x = acc[mi][ni][half*2 + 0];
                    v.y = acc[mi][ni][half*2 + 1];
                    *(float2*)&Ap[((size_t)h*BT + bt)*KVD + cc] = v;
                }
            }
        }
    }
}

// ---------------- FFN1 split-K: A[448,Kd] x B[Kd,Nc], 64x256 tiles, partials ----------------
__global__ __launch_bounds__(256, 2) void gemm_tc_sk(
    const float* __restrict__ A, const float* __restrict__ Bw,
    float* __restrict__ Cp, int Nc, int Kd)
{
    extern __shared__ uint32_t sm[];
    uint32_t* As = sm;
    uint32_t* Bs = sm + 2*AP_A_WORDS;
    uint32_t sA = (uint32_t)__cvta_generic_to_shared(As);
    uint32_t sB = (uint32_t)__cvta_generic_to_shared(Bs);

    int tid = threadIdx.x;
    int lane = tid & 31, w = tid >> 5;
    int warpM = w & 1, warpN = w >> 1;
    int lg = lane >> 2, lt = lane & 3;
    int colBase = blockIdx.x * 256;
    int rowBase = blockIdx.y * 64;
    int s = blockIdx.z;
    int kOff = s * (Kd >> 1);

    float acc[2][8][4];
    #pragma unroll
    for (int mi = 0; mi < 2; mi++)
        #pragma unroll
        for (int ni = 0; ni < 8; ni++)
            #pragma unroll
            for (int q = 0; q < 4; q++) acc[mi][ni][q] = 0.f;

    auto loadA = [&](int kc, int buf) {
        int k0 = kOff + kc * 32;
        #pragma unroll
        for (int i = 0; i < 2; i++) {
            int idx = tid + i * 256;
            int r = idx >> 3, c4 = (idx & 7) << 2;
            cpa16(sA + ((buf*AP_A_WORDS + r*SC_A_STRIDE + c4) << 2),
                  A + (size_t)(rowBase + r)*Kd + k0 + c4, 16u);
        }
    };
    auto loadB = [&](int kc, int buf) {
        int k0 = kOff + kc * 32;
        #pragma unroll
        for (int i = 0; i < 8; i++) {
            int idx = tid + i * 256;
            int r = idx >> 6, c4 = (idx & 63) << 2;
            cpa16(sB + ((buf*AP_B_WORDS + r*AP_B_STRIDE + c4) << 2),
                  Bw + (size_t)(k0 + r)*Nc + colBase + c4, 16u);
        }
    };

    const int NC = (Kd >> 1) / 32;
    loadA(0, 0); loadB(0, 0); cpa_commit();
    for (int kc = 0; kc < NC; kc++) {
        int cur = kc & 1;
        if (kc + 1 < NC) {
            loadA(kc+1, cur^1); loadB(kc+1, cur^1); cpa_commit();
            cpa_wait1();
        } else {
            cpa_wait0();
        }
        __syncthreads();
        const uint32_t* Ab = As + cur*AP_A_WORDS;
        const uint32_t* Bb = Bs + cur*AP_B_WORDS;
        #pragma unroll
        for (int ks = 0; ks < 4; ks++) {
            int kb = ks * 8;
            uint32_t a[2][4];
            #pragma unroll
            for (int mi = 0; mi < 2; mi++) {
                int r = warpM*32 + mi*16 + lg;
                a[mi][0] = Ab[r*SC_A_STRIDE + kb + lt];
                a[mi][1] = Ab[(r+8)*SC_A_STRIDE + kb + lt];
                a[mi][2] = Ab[r*SC_A_STRIDE + kb + lt + 4];
                a[mi][3] = Ab[(r+8)*SC_A_STRIDE + kb + lt + 4];
            }
            #pragma unroll
            for (int ni = 0; ni < 8; ni++) {
                int n = warpN*64 + ni*8 + lg;
                uint32_t b0 = Bb[(kb + lt)*AP_B_STRIDE + n];
                uint32_t b1 = Bb[(kb + lt + 4)*AP_B_STRIDE + n];
                mma_tf32(acc[0][ni], a[0], b0, b1);
                mma_tf32(acc[1][ni], a[1], b0, b1);
            }
        }
        __syncthreads();
    }

    float* Cs = Cp + (size_t)s * BT * Nc;
    #pragma unroll
    for (int mi = 0; mi < 2; mi++) {
        #pragma unroll
        for (int ni = 0; ni < 8; ni++) {
            int cc = colBase + warpN*64 + ni*8 + lt*2;
            #pragma unroll
            for (int half = 0; half < 2; half++) {
                int r = rowBase + warpM*32 + mi*16 + lg + half*8;
                float2 v;
                v.x = acc[mi][ni][half*2 + 0];
                v.y = acc[mi][ni][half*2 + 1];
                *(float2*)&Cs[(size_t)r*Nc + cc] = v;
            }
        }
    }
}

// ---------------- FFN2 split-K: 64x64 tiles. grid (Nc/64, 448/64, 2) ----------------
__global__ __launch_bounds__(256) void gemm_n64_sk(
    const float* __restrict__ A, const float* __restrict__ Bw,
    float* __restrict__ Cp, int Nc, int Kd)
{
    __shared__ uint32_t As[2][64][36];
    __shared__ uint32_t Bs[2][32][72];
    uint32_t sA = (uint32_t)__cvta_generic_to_shared(&As[0][0][0]);
    uint32_t sB = (uint32_t)__cvta_generic_to_shared(&Bs[0][0][0]);

    int tid = threadIdx.x;
    int lane = tid & 31, w = tid >> 5;
    int warpM = w & 1, warpN = w >> 1;
    int lg = lane >> 2, lt = lane & 3;
    int colBase = blockIdx.x * 64;
    int rowBase = blockIdx.y * 64;
    int s = blockIdx.z;
    int kOff = s * (Kd >> 1);

    float acc[2][2][4];
    #pragma unroll
    for (int mi = 0; mi < 2; mi++)
        #pragma unroll
        for (int ni = 0; ni < 2; ni++)
            #pragma unroll
            for (int q = 0; q < 4; q++) acc[mi][ni][q] = 0.f;

    auto loadStage = [&](int kc, int buf) {
        int k0 = kOff + kc * 32;
        #pragma unroll
        for (int i = 0; i < 2; i++) {
            int idx = tid + i * 256;
            int r = idx >> 3, c4 = (idx & 7) << 2;
            cpa16(sA + ((buf*64*36 + r*36 + c4) << 2),
                  A + (size_t)(rowBase + r)*Kd + k0 + c4, 16u);
        }
        #pragma unroll
        for (int i = 0; i < 2; i++) {
            int idx = tid + i * 256;
            int r = idx >> 4, c4 = (idx & 15) << 2;
            cpa16(sB + ((buf*32*72 + r*72 + c4) << 2),
                  Bw + (size_t)(k0 + r)*Nc + colBase + c4, 16u);
        }
        cpa_commit();
    };

    const int NC = (Kd >> 1) / 32;
    loadStage(0, 0);
    for (int kc = 0; kc < NC; kc++) {
        int cur = kc & 1;
        if (kc + 1 < NC) { loadStage(kc+1, cur^1); cpa_wait1(); }
        else             { cpa_wait0(); }
        __syncthreads();
        #pragma unroll
        for (int ks = 0; ks < 4; ks++) {
            int kb = ks * 8;
            uint32_t a[2][4];
            #pragma unroll
            for (int mi = 0; mi < 2; mi++) {
                int r = warpM*32 + mi*16 + lg;
                a[mi][0] = As[cur][r][kb + lt];
                a[mi][1] = As[cur][r+8][kb + lt];
                a[mi][2] = As[cur][r][kb + lt + 4];
                a[mi][3] = As[cur][r+8][kb + lt + 4];
            }
            #pragma unroll
            for (int ni = 0; ni < 2; ni++) {
                int n = warpN*16 + ni*8 + lg;
                uint32_t b0 = Bs[cur][kb + lt][n];
                uint32_t b1 = Bs[cur][kb + lt + 4][n];
                mma_tf32(acc[0][ni], a[0], b0, b1);
                mma_tf32(acc[1][ni], a[1], b0, b1);
            }
        }
        __syncthreads();
    }

    float* Cs = Cp + (size_t)s * BT * Nc;
    #pragma unroll
    for (int mi = 0; mi < 2; mi++) {
        #pragma unroll
        for (int ni = 0; ni < 2; ni++) {
            int cc = colBase + warpN*16 + ni*8 + lt*2;
            #pragma unroll
            for (int half = 0; half < 2; half++) {
                int r = rowBase + warpM*32 + mi*16 + lg + half*8;
                float2 v;
                v.x = acc[mi][ni][half*2 + 0];
                v.y = acc[mi][ni][half*2 + 1];
                *(float2*)&Cs[(size_t)r*Nc + cc] = v;
            }
        }
    }
}

// ---------------- split-K reduce: C = p[0] + p[1] + bias (+ReLU) ----------------
template<bool RELU>
__global__ __launch_bounds__(256) void reduce_sk_kernel(
    const float* __restrict__ p, const float* __restrict__ bias,
    float* __restrict__ C, int Nc)
{
    int r = blockIdx.x;
    const float4* p0 = (const float4*)(p + (size_t)r * Nc);
    const float4* p1 = (const float4*)(p + (size_t)(BT + r) * Nc);
    const float4* b4 = (const float4*)bias;
    float4* c4 = (float4*)(C + (size_t)r * Nc);
    for (int i = threadIdx.x; i < (Nc >> 2); i += 256) {
        float4 a = p0[i], b = p1[i], bi = b4[i];
        float4 v;
        v.x = a.x + b.x + bi.x; v.y = a.y + b.y + bi.y;
        v.z = a.z + b.z + bi.z; v.w = a.w + b.w + bi.w;
        if (RELU) {
            v.x = fmaxf(v.x, 0.f); v.y = fmaxf(v.y, 0.f);
            v.z = fmaxf(v.z, 0.f); v.w = fmaxf(v.w, 0.f);
        }
        c4[i] = v;
    }
}

// ---------------- attn_out = A'[h] . WV_h + bV_h via mma (64x64 tiles/head) ----------------
__global__ __launch_bounds__(256) void attnout_mma_kernel(
    const float* __restrict__ Ap, const float* __restrict__ WV,
    const float* __restrict__ bV, float* __restrict__ O)
{
    __shared__ uint32_t As[2][64][36];
    __shared__ uint32_t Bs[2][32][72];
    uint32_t sA = (uint32_t)__cvta_generic_to_shared(&As[0][0][0]);
    uint32_t sB = (uint32_t)__cvta_generic_to_shared(&Bs[0][0][0]);

    int tid = threadIdx.x;
    int lane = tid & 31, w = tid >> 5;
    int warpM = w & 1, warpN = w >> 1;
    int lg = lane >> 2, lt = lane & 3;
    int rowBase = blockIdx.x * 64;
    int h = blockIdx.y;

    const float* Ag = Ap + (size_t)h * BT * KVD;
    const float* Bg = WV + h * HD_;

    float acc[2][2][4];
    #pragma unroll
    for (int mi = 0; mi < 2; mi++)
        #pragma unroll
        for (int ni = 0; ni < 2; ni++)
            #pragma unroll
            for (int q = 0; q < 4; q++) acc[mi][ni][q] = 0.f;

    auto loadStage = [&](int kc, int buf) {
        int k0 = kc * 32;
        #pragma unroll
        for (int i = 0; i < 2; i++) {
            int idx = tid + i * 256;
            int r = idx >> 3, c4 = (idx & 7) << 2;
            cpa16(sA + ((buf*64*36 + r*36 + c4) << 2),
                  Ag + (size_t)(rowBase + r)*KVD + k0 + c4, 16u);
        }
        #pragma unroll
        for (int i = 0; i < 2; i++) {
            int idx = tid + i * 256;
            int r = idx >> 4, c4 = (idx & 15) << 2;
            cpa16(sB + ((buf*32*72 + r*72 + c4) << 2),
                  Bg + (size_t)(k0 + r)*QD + c4, 16u);
        }
        cpa_commit();
    };

    const int NC = KVD / 32;
    loadStage(0, 0);
    for (int kc = 0; kc < NC; kc++) {
        int cur = kc & 1;
        if (kc + 1 < NC) { loadStage(kc+1, cur^1); cpa_wait1(); }
        else             { cpa_wait0(); }
        __syncthreads();
        #pragma unroll
        for (int ks = 0; ks < 4; ks++) {
            int kb = ks * 8;
            uint32_t a[2][4];
            #pragma unroll
            for (int mi = 0; mi < 2; mi++) {
                int r = warpM*32 + mi*16 + lg;
                a[mi][0] = As[cur][r][kb + lt];
                a[mi][1] = As[cur][r+8][kb + lt];
                a[mi][2] = As[cur][r][kb + lt + 4];
                a[mi][3] = As[cur][r+8][kb + lt + 4];
            }
            #pragma unroll
            for (int ni = 0; ni < 2; ni++) {
                int n = warpN*16 + ni*8 + lg;
                uint32_t b0 = Bs[cur][kb + lt][n];
                uint32_t b1 = Bs[cur][kb + lt + 4][n];
                mma_tf32(acc[0][ni], a[0], b0, b1);
                mma_tf32(acc[1][ni], a[1], b0, b1);
            }
        }
        __syncthreads();
    }

    #pragma unroll
    for (int mi = 0; mi < 2; mi++) {
        #pragma unroll
        for (int ni = 0; ni < 2; ni++) {
            int cc = warpN*16 + ni*8 + lt*2;
            float bi0 = bV[h*HD_ + cc], bi1 = bV[h*HD_ + cc + 1];
            #pragma unroll
            for (int half = 0; half < 2; half++) {
                int r = rowBase + warpM*32 + mi*16 + lg + half*8;
                float2 v;
                v.x = acc[mi][ni][half*2 + 0] + bi0;
                v.y = acc[mi][ni][half*2 + 1] + bi1;
                *(float2*)&O[(size_t)r*QD + h*HD_ + cc] = v;
            }
        }
    }
}

// ---------------- residual add + LayerNorm ----------------
__global__ __launch_bounds__(256) void add_ln_kernel(
    const float* __restrict__ A, const float* __restrict__ Bv,
    const float* __restrict__ g, const float* __restrict__ be,
    float* __restrict__ out)
{
    __shared__ float xs[QD];
    __shared__ float red[256];
    int r = blockIdx.x, tid = threadIdx.x;
    float lsum = 0.f;
    for (int i = tid; i < QD; i += 256) {
        float v = A[(size_t)r*QD + i] + Bv[(size_t)r*QD + i];
        xs[i] = v;
        lsum += v;
    }
    red[tid] = lsum; __syncthreads();
    for (int s = 128; s > 0; s >>= 1) {
        if (tid < s) red[tid] += red[tid + s];
        __syncthreads();
    }
    float mu = red[0] / QD; __syncthreads();
    float lv = 0.f;
    for (int i = tid; i < QD; i += 256) {
        float d0 = xs[i] - mu;
        lv += d0 * d0;
    }
    red[tid] = lv; __syncthreads();
    for (int s = 128; s > 0; s >>= 1) {
        if (tid < s) red[tid] += red[tid + s];
        __syncthreads();
    }
    float inv = rsqrtf(red[0] / QD + EPS_); __syncthreads();
    for (int i = tid; i < QD; i += 256)
        out[(size_t)r*QD + i] = (xs[i] - mu) * inv * g[i] + be[i];
}

// ---------------- launch ----------------
extern "C" void kernel_launch(void* const* d_in, const int* in_sizes, int n_in,
                              void* d_out, int out_size)
{
    const float* X   = (const float*)d_in[0];
    const float* KV  = (const float*)d_in[1];
    const float* WQ  = (const float*)d_in[2];
    const float* bQ  = (const float*)d_in[3];
    const float* WK  = (const float*)d_in[4];
    const float* bK  = (const float*)d_in[5];
    const float* WV  = (const float*)d_in[6];
    const float* bV  = (const float*)d_in[7];
    const float* W1  = (const float*)d_in[8];
    const float* b1  = (const float*)d_in[9];
    const float* W2  = (const float*)d_in[10];
    const float* b2  = (const float*)d_in[11];
    const float* g1  = (const float*)d_in[12];
    const float* be1 = (const float*)d_in[13];
    const float* g2  = (const float*)d_in[14];
    const float* be2 = (const float*)d_in[15];

    float* out   = (float*)d_out;
    float* attnw = out + (size_t)BT*QD;

    float *Qp, *Qtp, *cp, *Sp, *App, *Aop, *X1, *Hm, *Fp, *P1, *P2;
    cudaGetSymbolAddress((void**)&Qp,  g_Q);
    cudaGetSymbolAddress((void**)&Qtp, g_Qt);
    cudaGetSymbolAddress((void**)&cp,  g_c);
    cudaGetSymbolAddress((void**)&Sp,  g_S);
    cudaGetSymbolAddress((void**)&App, g_Ap);
    cudaGetSymbolAddress((void**)&Aop, g_attn);
    cudaGetSymbolAddress((void**)&X1,  g_x1);
    cudaGetSymbolAddress((void**)&Hm,  g_h);
    cudaGetSymbolAddress((void**)&Fp,  g_ff);
    cudaGetSymbolAddress((void**)&P1,  g_p1);
    cudaGetSymbolAddress((void**)&P2,  g_p2);

    cudaFuncSetAttribute(scores_kernel, cudaFuncAttributeMaxDynamicSharedMemorySize, S2_SMEM_BYTES);
    cudaFuncSetAttribute(aprime_kernel, cudaFuncAttributeMaxDynamicSharedMemorySize, A2_SMEM_BYTES);
    cudaFuncSetAttribute(gemm_tc_sk,    cudaFuncAttributeMaxDynamicSharedMemorySize, AP_SMEM_BYTES);

    // Q projection (one GEMM per expert token)
    qproj_kernel<<<dim3(T_, QD/128), 256>>>(X, WQ, bQ, Qp);

    // Qt = Q . WK^T (per head), c = Q . bK
    qt_kernel<<<dim3(H_, BT/64, KVD/64), 256>>>(Qp, WK, Qtp);
    crow_kernel<<<dim3(BT, H_), 32>>>(Qp, bK, cp);

    // scores = Qt . X^T  (96x256 tiles, 4-stage)
    scores_kernel<<<dim3(M_/256, 2, B_), 256, S2_SMEM_BYTES>>>(Qtp, KV, Sp);

    // attn_w = softmax((scores + c)/8) -> written directly to output
    softmax_kernel<<<B_*TH, 256>>>(Sp, cp, attnw);

    // A' = P . X  (96x256 tiles, 4-stage)
    aprime_kernel<<<dim3(KVD/256, 2, B_), 256, A2_SMEM_BYTES>>>(attnw, KV, App);

    // attn_out = A' . WV + bV  (mma, per-head 64x64 tiles)
    attnout_mma_kernel<<<dim3(BT/64, H_), 256>>>(App, WV, bV, Aop);

    // x1 = LN(tokens + attn_out)
    add_ln_kernel<<<BT, 256>>>(X, Aop, g1, be1, X1);

    // FFN1: split-K x2 + reduce(ReLU+bias)
    gemm_tc_sk<<<dim3(FF_/256, BT/64, 2), 256, AP_SMEM_BYTES>>>(X1, W1, P1, FF_, QD);
    reduce_sk_kernel<true><<<BT, 256>>>(P1, b1, Hm, FF_);

    // FFN2: split-K x2 (64x64 tiles) + reduce(bias)
    gemm_n64_sk<<<dim3(QD/64, BT/64, 2), 256>>>(Hm, W2, P2, QD, FF_);
    reduce_sk_kernel<false><<<BT, 256>>>(P2, b2, Fp, QD);

    // out = LN(x1 + ff)
    add_ln_kernel<<<BT, 256>>>(X1, Fp, g2, be2, out);
}